// round 5
// baseline (speedup 1.0000x reference)
#include <cuda_runtime.h>
#include <math.h>

#define NN 50000
#define NE 800000
#define IN_DIM 128
#define HID 32
#define HEADS 8
#define F1DIM 256
#define ODIM 64
#define NEG 0.2f

// ---------------- scratch (device globals; no allocation) ----------------
__device__ alignas(16) float g_f1[(size_t)NN * F1DIM];   // 51.2 MB
__device__ alignas(16) float g_h [(size_t)NN * F1DIM];   // 51.2 MB (bias -> agg1; ELU fused into GEMM2 load)
__device__ alignas(16) float g_f2[(size_t)NN * ODIM];    // 12.8 MB
__device__ float g_el1[NN * HEADS];
__device__ float g_er1[NN * HEADS];
__device__ float g_s1 [NN * HEADS];
__device__ float g_a1 [(size_t)NE * HEADS];              // 25.6 MB
__device__ float g_el2[NN];
__device__ float g_er2[NN];
__device__ float g_s2 [NN];
__device__ float g_a2 [NE];

__device__ __forceinline__ float lrelu(float x) { return x >= 0.f ? x : NEG * x; }

__device__ __forceinline__ void red_add_f4(float4* p, float4 v) {
    asm volatile("red.global.add.v4.f32 [%0], {%1,%2,%3,%4};"
                 :: "l"((float*)p), "f"(v.x), "f"(v.y), "f"(v.z), "f"(v.w) : "memory");
}

// ---------------- GEMM: C[M,N] = A[M,K] @ B[K,N], row-major ----------------
// 256 threads; BM*BK must be 1024 (one float4 A-load per thread).
// ELUA: apply ELU to A elements on load (fuses layer-1 activation into GEMM2).
template<int BM, int BN, int BK, int TM, int TN, bool ELUA>
__global__ void __launch_bounds__(256, 2)
gemm_kernel(const float* __restrict__ A, const float* __restrict__ B,
            float* __restrict__ C, int M, int N, int K) {
    __shared__ float As[BK][BM];
    __shared__ float Bs[BK][BN];
    const int tid  = threadIdx.x;
    const int tcol = tid % (BN / TN);
    const int trow = tid / (BN / TN);
    const int rowBase = blockIdx.y * BM;
    const int colBase = blockIdx.x * BN;

    float acc[TM][TN];
#pragma unroll
    for (int i = 0; i < TM; i++)
#pragma unroll
        for (int j = 0; j < TN; j++) acc[i][j] = 0.f;

    const int ar = tid >> 1;          // A row within tile (0..127)
    const int ak = (tid & 1) * 4;     // A k-offset (0 or 4)

    for (int k0 = 0; k0 < K; k0 += BK) {
        // load A tile (transposed into As)
        {
            int gr = rowBase + ar;
            float4 av = make_float4(0.f, 0.f, 0.f, 0.f);
            if (gr < M) av = *(const float4*)&A[(size_t)gr * K + k0 + ak];
            if (ELUA) {
                av.x = av.x > 0.f ? av.x : expm1f(av.x);
                av.y = av.y > 0.f ? av.y : expm1f(av.y);
                av.z = av.z > 0.f ? av.z : expm1f(av.z);
                av.w = av.w > 0.f ? av.w : expm1f(av.w);
            }
            As[ak + 0][ar] = av.x;
            As[ak + 1][ar] = av.y;
            As[ak + 2][ar] = av.z;
            As[ak + 3][ar] = av.w;
        }
        // load B tile
        if (tid * 4 < BK * BN) {
            int br = (tid * 4) / BN, bc = (tid * 4) % BN;
            *(float4*)&Bs[br][bc] = *(const float4*)&B[(size_t)(k0 + br) * N + colBase + bc];
        }
        __syncthreads();
#pragma unroll
        for (int k = 0; k < BK; k++) {
            float a[TM], b[TN];
#pragma unroll
            for (int i = 0; i < TM; i++) a[i] = As[k][trow * TM + i];
#pragma unroll
            for (int j = 0; j < TN; j++) b[j] = Bs[k][tcol * TN + j];
#pragma unroll
            for (int i = 0; i < TM; i++)
#pragma unroll
                for (int j = 0; j < TN; j++) acc[i][j] += a[i] * b[j];
        }
        __syncthreads();
    }
#pragma unroll
    for (int i = 0; i < TM; i++) {
        int gr = rowBase + trow * TM + i;
        if (gr >= M) continue;
        float* cp = &C[(size_t)gr * N + colBase + tcol * TN];
#pragma unroll
        for (int j = 0; j < TN; j += 4)
            *(float4*)&cp[j] = make_float4(acc[i][j], acc[i][j+1], acc[i][j+2], acc[i][j+3]);
    }
}

// ---------------- per-node attention halves ----------------
__global__ void attn_lr1(const float* __restrict__ al, const float* __restrict__ ar) {
    int i = blockIdx.x * blockDim.x + threadIdx.x;   // over NN*HEADS
    if (i >= NN * HEADS) return;
    int h = i & (HEADS - 1);
    const float4* fp = (const float4*)(g_f1 + (size_t)(i >> 3) * F1DIM + h * HID);
    const float4* alp = (const float4*)(al + h * HID);
    const float4* arp = (const float4*)(ar + h * HID);
    float sl = 0.f, sr = 0.f;
#pragma unroll
    for (int q = 0; q < 8; q++) {
        float4 v = fp[q], a = alp[q], b = arp[q];
        sl += v.x * a.x + v.y * a.y + v.z * a.z + v.w * a.w;
        sr += v.x * b.x + v.y * b.y + v.z * b.z + v.w * b.w;
    }
    g_el1[i] = sl;
    g_er1[i] = sr;
}

__global__ void attn_lr2(const float* __restrict__ al, const float* __restrict__ ar) {
    int i = blockIdx.x * blockDim.x + threadIdx.x;   // over NN
    if (i >= NN) return;
    const float4* fp = (const float4*)(g_f2 + (size_t)i * ODIM);
    const float4* alp = (const float4*)al;
    const float4* arp = (const float4*)ar;
    float sl = 0.f, sr = 0.f;
#pragma unroll
    for (int q = 0; q < 16; q++) {
        float4 v = fp[q], a = alp[q], b = arp[q];
        sl += v.x * a.x + v.y * a.y + v.z * a.z + v.w * a.w;
        sr += v.x * b.x + v.y * b.y + v.z * b.z + v.w * b.w;
    }
    g_el2[i] = sl;
    g_er2[i] = sr;
}

// ---------------- init: seed accumulators with bias, zero softmax sums ----------------
__global__ void init_h(const float* __restrict__ b1) {
    int i = blockIdx.x * blockDim.x + threadIdx.x;   // over NN*F1DIM
    if (i < NN * F1DIM) g_h[i] = b1[i & (F1DIM - 1)];
    if (i < NN * HEADS) g_s1[i] = 0.f;
}
__global__ void init_out(float* __restrict__ out, const float* __restrict__ b2) {
    int i = blockIdx.x * blockDim.x + threadIdx.x;   // over NN*ODIM
    if (i < NN * ODIM) out[i] = b2[i & (ODIM - 1)];
    if (i < NN) g_s2[i] = 0.f;
}

// ---------------- edge passes (no max-shift: logits are O(1) by construction) --------
__global__ void edge_sum1(const int* __restrict__ src, const int* __restrict__ dst) {
    int idx = blockIdx.x * blockDim.x + threadIdx.x;  // over NE*HEADS
    if (idx >= NE * HEADS) return;
    int e = idx >> 3, h = idx & 7;
    int s = src[e], d = dst[e];
    float a = __expf(lrelu(g_el1[s * HEADS + h] + g_er1[d * HEADS + h]));
    g_a1[idx] = a;                    // layout [e][h] == idx
    atomicAdd(&g_s1[d * HEADS + h], a);
}
__global__ void inv_s1() {
    int i = blockIdx.x * blockDim.x + threadIdx.x;
    if (i >= NN * HEADS) return;
    float s = g_s1[i];
    g_s1[i] = s > 0.f ? 1.f / s : 1.f;
}
__global__ void edge_msg1(const int* __restrict__ src, const int* __restrict__ dst) {
    int idx = blockIdx.x * blockDim.x + threadIdx.x;  // over NE*HEADS (one (e,h) per thread)
    if (idx >= NE * HEADS) return;
    int e = idx >> 3, h = idx & 7;
    int s = src[e], d = dst[e];
    float alpha = g_a1[idx] * g_s1[d * HEADS + h];
    const float4* fp = (const float4*)&g_f1[(size_t)s * F1DIM + h * HID];
    float4* op = (float4*)&g_h[(size_t)d * F1DIM + h * HID];
#pragma unroll
    for (int q = 0; q < 8; q++) {
        float4 v = fp[q];
        red_add_f4(op + q, make_float4(v.x * alpha, v.y * alpha, v.z * alpha, v.w * alpha));
    }
}

__global__ void edge_sum2(const int* __restrict__ src, const int* __restrict__ dst) {
    int e = blockIdx.x * blockDim.x + threadIdx.x;   // over NE
    if (e >= NE) return;
    int s = src[e], d = dst[e];
    float a = __expf(lrelu(g_el2[s] + g_er2[d]));
    g_a2[e] = a;
    atomicAdd(&g_s2[d], a);
}
__global__ void inv_s2() {
    int i = blockIdx.x * blockDim.x + threadIdx.x;
    if (i >= NN) return;
    float s = g_s2[i];
    g_s2[i] = s > 0.f ? 1.f / s : 1.f;
}
__global__ void edge_msg2(const int* __restrict__ src, const int* __restrict__ dst,
                          float* __restrict__ out) {
    int idx = blockIdx.x * blockDim.x + threadIdx.x;  // over NE*4 (16 floats per thread)
    if (idx >= NE * 4) return;
    int e = idx >> 2, q = idx & 3;
    int s = src[e], d = dst[e];
    float alpha = g_a2[e] * g_s2[d];
    const float4* fp = (const float4*)&g_f2[(size_t)s * ODIM + q * 16];
    float4* op = (float4*)&out[(size_t)d * ODIM + q * 16];
#pragma unroll
    for (int j = 0; j < 4; j++) {
        float4 v = fp[j];
        red_add_f4(op + j, make_float4(v.x * alpha, v.y * alpha, v.z * alpha, v.w * alpha));
    }
}

// ---------------- launch ----------------
extern "C" void kernel_launch(void* const* d_in, const int* in_sizes, int n_in,
                              void* d_out, int out_size) {
    const float* feat = (const float*)d_in[0];
    const int*   src  = (const int*)  d_in[1];
    const int*   dst  = (const int*)  d_in[2];
    const float* W1   = (const float*)d_in[3];
    const float* al1  = (const float*)d_in[4];
    const float* ar1  = (const float*)d_in[5];
    const float* b1   = (const float*)d_in[6];
    const float* W2   = (const float*)d_in[7];
    const float* al2  = (const float*)d_in[8];
    const float* ar2  = (const float*)d_in[9];
    const float* b2   = (const float*)d_in[10];
    float* out = (float*)d_out;

    float *pf1, *ph, *pf2;
    cudaGetSymbolAddress((void**)&pf1, g_f1);
    cudaGetSymbolAddress((void**)&ph,  g_h);
    cudaGetSymbolAddress((void**)&pf2, g_f2);

    const int T = 256;
    auto cdiv = [](long long a, long long b) { return (int)((a + b - 1) / b); };

    // Layer 1
    gemm_kernel<128,128,8,8,8,false><<<dim3(F1DIM/128, cdiv(NN,128)), 256>>>(feat, W1, pf1, NN, F1DIM, IN_DIM);
    attn_lr1<<<cdiv(NN*HEADS, T), T>>>(al1, ar1);
    init_h<<<cdiv((long long)NN*F1DIM, T), T>>>(b1);
    edge_sum1<<<cdiv((long long)NE*HEADS, T), T>>>(src, dst);
    inv_s1<<<cdiv(NN*HEADS, T), T>>>();
    edge_msg1<<<cdiv((long long)NE*HEADS, T), T>>>(src, dst);

    // Layer 2 (ELU fused into GEMM2's A-tile load)
    gemm_kernel<128,64,8,8,4,true><<<dim3(ODIM/64, cdiv(NN,128)), 256>>>(ph, W2, pf2, NN, ODIM, F1DIM);
    attn_lr2<<<cdiv(NN, T), T>>>(al2, ar2);
    init_out<<<cdiv((long long)NN*ODIM, T), T>>>(out, b2);
    edge_sum2<<<cdiv(NE, T), T>>>(src, dst);
    inv_s2<<<cdiv(NN, T), T>>>();
    edge_msg2<<<cdiv((long long)NE*4, T), T>>>(src, dst, out);
}

// round 8
// speedup vs baseline: 1.8222x; 1.8222x over previous
#include <cuda_runtime.h>
#include <math.h>

#define NN 50000
#define NE 800000
#define IN_DIM 128
#define HID 32
#define HEADS 8
#define F1DIM 256
#define ODIM 64
#define NEG 0.2f
#define FULL 0xffffffffu

// ---------------- scratch (device globals; no allocation) ----------------
__device__ alignas(16) float g_f1[(size_t)NN * F1DIM];   // 51.2 MB
__device__ alignas(16) float g_h [(size_t)NN * F1DIM];   // 51.2 MB
__device__ alignas(16) float g_f2[(size_t)NN * ODIM];    // 12.8 MB
__device__ float g_el1[NN * HEADS];
__device__ float g_er1[NN * HEADS];
__device__ float g_el2[NN];
__device__ float g_er2[NN];
// CSR (dst-sorted), built on device each call
__device__ int g_cnt [NN];
__device__ int g_off [NN + 1];
__device__ int g_pos [NN];
__device__ int g_psrc[NE];     // src[e] permuted into dst-sorted order

__device__ __forceinline__ float lrelu(float x) { return x >= 0.f ? x : NEG * x; }

// ---------------- CSR build ----------------
__global__ void zero_cnt() {
    int i = blockIdx.x * blockDim.x + threadIdx.x;
    if (i < NN) g_cnt[i] = 0;
}
__global__ void count_dst(const int* __restrict__ dst) {
    int e = blockIdx.x * blockDim.x + threadIdx.x;
    if (e < NE) atomicAdd(&g_cnt[dst[e]], 1);
}
// single block, 1024 threads: exclusive scan of g_cnt -> g_off (+ copy to g_pos)
__global__ void scan_off() {
    __shared__ int wsum[32];
    const int t = threadIdx.x;
    const int C = (NN + 1023) / 1024;
    const int base = t * C;
    int s = 0;
    for (int j = 0; j < C; j++) { int idx = base + j; if (idx < NN) s += g_cnt[idx]; }
    int lane = t & 31, wid = t >> 5;
    int v = s;
#pragma unroll
    for (int o = 1; o < 32; o <<= 1) { int n = __shfl_up_sync(FULL, v, o); if (lane >= o) v += n; }
    if (lane == 31) wsum[wid] = v;
    __syncthreads();
    if (wid == 0) {
        int w = wsum[lane];
#pragma unroll
        for (int o = 1; o < 32; o <<= 1) { int n = __shfl_up_sync(FULL, w, o); if (lane >= o) w += n; }
        wsum[lane] = w;
    }
    __syncthreads();
    int run = (v - s) + (wid > 0 ? wsum[wid - 1] : 0);   // exclusive prefix of this chunk
    for (int j = 0; j < C; j++) {
        int idx = base + j;
        if (idx < NN) { g_off[idx] = run; g_pos[idx] = run; run += g_cnt[idx]; }
    }
    if (t == 1023) g_off[NN] = NE;
}
__global__ void place_edges(const int* __restrict__ src, const int* __restrict__ dst) {
    int e = blockIdx.x * blockDim.x + threadIdx.x;
    if (e >= NE) return;
    int slot = atomicAdd(&g_pos[dst[e]], 1);
    g_psrc[slot] = src[e];
}

// ---------------- GEMM: C[M,N] = A[M,K] @ B[K,N], row-major ----------------
template<int BM, int BN, int BK, int TM, int TN, bool ELUA>
__global__ void __launch_bounds__(256, 2)
gemm_kernel(const float* __restrict__ A, const float* __restrict__ B,
            float* __restrict__ C, int M, int N, int K) {
    __shared__ float As[BK][BM];
    __shared__ float Bs[BK][BN];
    const int tid  = threadIdx.x;
    const int tcol = tid % (BN / TN);
    const int trow = tid / (BN / TN);
    const int rowBase = blockIdx.y * BM;
    const int colBase = blockIdx.x * BN;

    float acc[TM][TN];
#pragma unroll
    for (int i = 0; i < TM; i++)
#pragma unroll
        for (int j = 0; j < TN; j++) acc[i][j] = 0.f;

    const int ar = tid >> 1;
    const int ak = (tid & 1) * 4;

    for (int k0 = 0; k0 < K; k0 += BK) {
        {
            int gr = rowBase + ar;
            float4 av = make_float4(0.f, 0.f, 0.f, 0.f);
            if (gr < M) av = *(const float4*)&A[(size_t)gr * K + k0 + ak];
            if (ELUA) {
                av.x = av.x > 0.f ? av.x : expm1f(av.x);
                av.y = av.y > 0.f ? av.y : expm1f(av.y);
                av.z = av.z > 0.f ? av.z : expm1f(av.z);
                av.w = av.w > 0.f ? av.w : expm1f(av.w);
            }
            As[ak + 0][ar] = av.x;
            As[ak + 1][ar] = av.y;
            As[ak + 2][ar] = av.z;
            As[ak + 3][ar] = av.w;
        }
        if (tid * 4 < BK * BN) {
            int br = (tid * 4) / BN, bc = (tid * 4) % BN;
            *(float4*)&Bs[br][bc] = *(const float4*)&B[(size_t)(k0 + br) * N + colBase + bc];
        }
        __syncthreads();
#pragma unroll
        for (int k = 0; k < BK; k++) {
            float a[TM], b[TN];
#pragma unroll
            for (int i = 0; i < TM; i++) a[i] = As[k][trow * TM + i];
#pragma unroll
            for (int j = 0; j < TN; j++) b[j] = Bs[k][tcol * TN + j];
#pragma unroll
            for (int i = 0; i < TM; i++)
#pragma unroll
                for (int j = 0; j < TN; j++) acc[i][j] += a[i] * b[j];
        }
        __syncthreads();
    }
#pragma unroll
    for (int i = 0; i < TM; i++) {
        int gr = rowBase + trow * TM + i;
        if (gr >= M) continue;
        float* cp = &C[(size_t)gr * N + colBase + tcol * TN];
#pragma unroll
        for (int j = 0; j < TN; j += 4)
            *(float4*)&cp[j] = make_float4(acc[i][j], acc[i][j+1], acc[i][j+2], acc[i][j+3]);
    }
}

// ---------------- per-node attention halves ----------------
__global__ void attn_lr1(const float* __restrict__ al, const float* __restrict__ ar) {
    int i = blockIdx.x * blockDim.x + threadIdx.x;   // over NN*HEADS
    if (i >= NN * HEADS) return;
    int h = i & (HEADS - 1);
    const float4* fp = (const float4*)(g_f1 + (size_t)(i >> 3) * F1DIM + h * HID);
    const float4* alp = (const float4*)(al + h * HID);
    const float4* arp = (const float4*)(ar + h * HID);
    float sl = 0.f, sr = 0.f;
#pragma unroll
    for (int q = 0; q < 8; q++) {
        float4 v = fp[q], a = alp[q], b = arp[q];
        sl += v.x * a.x + v.y * a.y + v.z * a.z + v.w * a.w;
        sr += v.x * b.x + v.y * b.y + v.z * b.z + v.w * b.w;
    }
    g_el1[i] = sl;
    g_er1[i] = sr;
}

__global__ void attn_lr2(const float* __restrict__ al, const float* __restrict__ ar) {
    int i = blockIdx.x * blockDim.x + threadIdx.x;   // over NN
    if (i >= NN) return;
    const float4* fp = (const float4*)(g_f2 + (size_t)i * ODIM);
    const float4* alp = (const float4*)al;
    const float4* arp = (const float4*)ar;
    float sl = 0.f, sr = 0.f;
#pragma unroll
    for (int q = 0; q < 16; q++) {
        float4 v = fp[q], a = alp[q], b = arp[q];
        sl += v.x * a.x + v.y * a.y + v.z * a.z + v.w * a.w;
        sr += v.x * b.x + v.y * b.y + v.z * b.z + v.w * b.w;
    }
    g_el2[i] = sl;
    g_er2[i] = sr;
}

// ---------------- layer-1 aggregation: one warp per dst node ----------------
// lane owns output floats [lane*8, lane*8+8) of the 256-dim row; head = lane/4.
__global__ void __launch_bounds__(256)
agg1(const float* __restrict__ b1) {
    int warp = (blockIdx.x * blockDim.x + threadIdx.x) >> 5;
    if (warp >= NN) return;
    const int lane = threadIdx.x & 31;
    const int node = warp;
    const int beg = g_off[node], end = g_off[node + 1];

    float er_h = (lane < 8) ? g_er1[node * HEADS + lane] : 0.f;

    // phase 1: softmax denominator per head; 4 edges/iter, lane groups of 8
    const int grp = lane >> 3;     // 0..3: edge offset
    const int hh  = lane & 7;      // head
    const float er_hh = __shfl_sync(FULL, er_h, hh);
    float ssum = 0.f;
    for (int i = beg + grp; i < end; i += 4) {
        int s = g_psrc[i];
        ssum += __expf(lrelu(g_el1[s * HEADS + hh] + er_hh));
    }
    ssum += __shfl_xor_sync(FULL, ssum, 8);
    ssum += __shfl_xor_sync(FULL, ssum, 16);   // lanes with same hh now hold full per-head sum
    float inv = 1.f / ssum;                     // unused if no edges

    const int h4 = lane >> 2;                   // my head
    const float inv_h = __shfl_sync(FULL, inv, h4);
    const float er_my = __shfl_sync(FULL, er_h, h4);

    // phase 2: weighted gather-accumulate
    float acc[8];
#pragma unroll
    for (int j = 0; j < 8; j++) acc[j] = 0.f;
    for (int i = beg; i < end; i++) {
        int s = g_psrc[i];
        float alpha = __expf(lrelu(g_el1[s * HEADS + h4] + er_my)) * inv_h;
        const float4* fp = (const float4*)&g_f1[(size_t)s * F1DIM + lane * 8];
        float4 v0 = fp[0], v1 = fp[1];
        acc[0] += alpha * v0.x; acc[1] += alpha * v0.y;
        acc[2] += alpha * v0.z; acc[3] += alpha * v0.w;
        acc[4] += alpha * v1.x; acc[5] += alpha * v1.y;
        acc[6] += alpha * v1.z; acc[7] += alpha * v1.w;
    }
    const float4* bp = (const float4*)&b1[lane * 8];
    float4 bb0 = bp[0], bb1 = bp[1];
    float4* op = (float4*)&g_h[(size_t)node * F1DIM + lane * 8];
    op[0] = make_float4(acc[0] + bb0.x, acc[1] + bb0.y, acc[2] + bb0.z, acc[3] + bb0.w);
    op[1] = make_float4(acc[4] + bb1.x, acc[5] + bb1.y, acc[6] + bb1.z, acc[7] + bb1.w);
}

// ---------------- layer-2 aggregation: one warp per dst node, 1 head ----------------
// lane owns output floats [lane*2, lane*2+2) of the 64-dim row.
__global__ void __launch_bounds__(256)
agg2(float* __restrict__ out, const float* __restrict__ b2) {
    int warp = (blockIdx.x * blockDim.x + threadIdx.x) >> 5;
    if (warp >= NN) return;
    const int lane = threadIdx.x & 31;
    const int node = warp;
    const int beg = g_off[node], end = g_off[node + 1];

    const float er = g_er2[node];

    // phase 1: denominator, 32 edges per iter
    float ssum = 0.f;
    for (int i = beg + lane; i < end; i += 32) {
        int s = g_psrc[i];
        ssum += __expf(lrelu(g_el2[s] + er));
    }
#pragma unroll
    for (int o = 16; o > 0; o >>= 1) ssum += __shfl_xor_sync(FULL, ssum, o);
    float inv = 1.f / ssum;

    // phase 2
    float a0 = 0.f, a1 = 0.f;
    for (int i = beg; i < end; i++) {
        int s = g_psrc[i];
        float alpha = __expf(lrelu(g_el2[s] + er)) * inv;
        float2 v = *(const float2*)&g_f2[(size_t)s * ODIM + lane * 2];
        a0 += alpha * v.x;
        a1 += alpha * v.y;
    }
    float2 bb = *(const float2*)&b2[lane * 2];
    *(float2*)&out[(size_t)node * ODIM + lane * 2] = make_float2(a0 + bb.x, a1 + bb.y);
}

// ---------------- launch ----------------
extern "C" void kernel_launch(void* const* d_in, const int* in_sizes, int n_in,
                              void* d_out, int out_size) {
    const float* feat = (const float*)d_in[0];
    const int*   src  = (const int*)  d_in[1];
    const int*   dst  = (const int*)  d_in[2];
    const float* W1   = (const float*)d_in[3];
    const float* al1  = (const float*)d_in[4];
    const float* ar1  = (const float*)d_in[5];
    const float* b1   = (const float*)d_in[6];
    const float* W2   = (const float*)d_in[7];
    const float* al2  = (const float*)d_in[8];
    const float* ar2  = (const float*)d_in[9];
    const float* b2   = (const float*)d_in[10];
    float* out = (float*)d_out;

    float *pf1, *ph, *pf2;
    cudaGetSymbolAddress((void**)&pf1, g_f1);
    cudaGetSymbolAddress((void**)&ph,  g_h);
    cudaGetSymbolAddress((void**)&pf2, g_f2);

    const int T = 256;
    auto cdiv = [](long long a, long long b) { return (int)((a + b - 1) / b); };

    // CSR build (shared by both layers)
    zero_cnt<<<cdiv(NN, T), T>>>();
    count_dst<<<cdiv(NE, T), T>>>(dst);
    scan_off<<<1, 1024>>>();
    place_edges<<<cdiv(NE, T), T>>>(src, dst);

    // Layer 1
    gemm_kernel<128,128,8,8,8,false><<<dim3(F1DIM/128, cdiv(NN,128)), 256>>>(feat, W1, pf1, NN, F1DIM, IN_DIM);
    attn_lr1<<<cdiv(NN*HEADS, T), T>>>(al1, ar1);
    agg1<<<cdiv((long long)NN*32, T), T>>>(b1);

    // Layer 2 (ELU fused into GEMM2's A-tile load)
    gemm_kernel<128,64,8,8,4,true><<<dim3(ODIM/64, cdiv(NN,128)), 256>>>(ph, W2, pf2, NN, ODIM, F1DIM);
    attn_lr2<<<cdiv(NN, T), T>>>(al2, ar2);
    agg2<<<cdiv((long long)NN*32, T), T>>>(out, b2);
}

// round 9
// speedup vs baseline: 1.8618x; 1.0217x over previous
#include <cuda_runtime.h>
#include <math.h>

#define NN 50000
#define NE 800000
#define IN_DIM 128
#define HID 32
#define HEADS 8
#define F1DIM 256
#define ODIM 64
#define NEG 0.2f
#define FULL 0xffffffffu

// ---------------- scratch (device globals; no allocation) ----------------
__device__ alignas(16) float g_f1[(size_t)NN * F1DIM];   // 51.2 MB
__device__ alignas(16) float g_h [(size_t)NN * F1DIM];   // 51.2 MB
__device__ alignas(16) float g_f2[(size_t)NN * ODIM];    // 12.8 MB
__device__ float g_el1[NN * HEADS];
__device__ float g_er1[NN * HEADS];
__device__ float g_el2[NN];
__device__ float g_er2[NN];
// CSR (dst-sorted), built on device each call
__device__ int g_cnt [NN];
__device__ int g_off [NN + 1];
__device__ int g_pos [NN];
__device__ int g_psrc[NE];     // src[e] permuted into dst-sorted order

__device__ __forceinline__ float lrelu(float x) { return x >= 0.f ? x : NEG * x; }

// ---------------- CSR build ----------------
__global__ void zero_cnt() {
    int i = blockIdx.x * blockDim.x + threadIdx.x;
    if (i < NN) g_cnt[i] = 0;
}
__global__ void count_dst(const int* __restrict__ dst) {
    int e = blockIdx.x * blockDim.x + threadIdx.x;
    if (e < NE) atomicAdd(&g_cnt[dst[e]], 1);
}
// single block, 1024 threads: exclusive scan of g_cnt -> g_off (+ copy to g_pos)
__global__ void scan_off() {
    __shared__ int wsum[32];
    const int t = threadIdx.x;
    const int C = (NN + 1023) / 1024;
    const int base = t * C;
    int s = 0;
    for (int j = 0; j < C; j++) { int idx = base + j; if (idx < NN) s += g_cnt[idx]; }
    int lane = t & 31, wid = t >> 5;
    int v = s;
#pragma unroll
    for (int o = 1; o < 32; o <<= 1) { int n = __shfl_up_sync(FULL, v, o); if (lane >= o) v += n; }
    if (lane == 31) wsum[wid] = v;
    __syncthreads();
    if (wid == 0) {
        int w = wsum[lane];
#pragma unroll
        for (int o = 1; o < 32; o <<= 1) { int n = __shfl_up_sync(FULL, w, o); if (lane >= o) w += n; }
        wsum[lane] = w;
    }
    __syncthreads();
    int run = (v - s) + (wid > 0 ? wsum[wid - 1] : 0);   // exclusive prefix of this chunk
    for (int j = 0; j < C; j++) {
        int idx = base + j;
        if (idx < NN) { g_off[idx] = run; g_pos[idx] = run; run += g_cnt[idx]; }
    }
    if (t == 1023) g_off[NN] = NE;
}
__global__ void place_edges(const int* __restrict__ src, const int* __restrict__ dst) {
    int e = blockIdx.x * blockDim.x + threadIdx.x;
    if (e >= NE) return;
    int slot = atomicAdd(&g_pos[dst[e]], 1);
    g_psrc[slot] = src[e];
}

// ---------------- GEMM: C[M,N] = A[M,K] @ B[K,N], row-major, reg-prefetch ----------------
// 256 threads; BM*BK == 1024 (one float4 A-load per thread). ELUA fuses layer-1 ELU.
template<int BM, int BN, int BK, int TM, int TN, bool ELUA>
__global__ void __launch_bounds__(256, 2)
gemm_kernel(const float* __restrict__ A, const float* __restrict__ B,
            float* __restrict__ C, int M, int N, int K) {
    __shared__ float As[BK][BM];
    __shared__ float Bs[BK][BN];
    const int tid  = threadIdx.x;
    const int tcol = tid % (BN / TN);
    const int trow = tid / (BN / TN);
    const int rowBase = blockIdx.y * BM;
    const int colBase = blockIdx.x * BN;

    const int ar  = tid >> 1;          // A row within tile (0..127)
    const int ak  = (tid & 1) * 4;     // A k-offset (0 or 4)
    const int agr = rowBase + ar;
    const bool doB = (tid * 4) < (BK * BN);
    const int br = (tid * 4) / BN, bc = (tid * 4) % BN;

    float acc[TM][TN];
#pragma unroll
    for (int i = 0; i < TM; i++)
#pragma unroll
        for (int j = 0; j < TN; j++) acc[i][j] = 0.f;

    // prefetch first tiles into registers
    float4 pa = make_float4(0.f, 0.f, 0.f, 0.f);
    float4 pb = make_float4(0.f, 0.f, 0.f, 0.f);
    if (agr < M) pa = *(const float4*)&A[(size_t)agr * K + ak];
    if (doB)     pb = *(const float4*)&B[(size_t)br * N + colBase + bc];

    for (int k0 = 0; k0 < K; k0 += BK) {
        float4 sa = pa;
        if (ELUA) {
            sa.x = sa.x > 0.f ? sa.x : expm1f(sa.x);
            sa.y = sa.y > 0.f ? sa.y : expm1f(sa.y);
            sa.z = sa.z > 0.f ? sa.z : expm1f(sa.z);
            sa.w = sa.w > 0.f ? sa.w : expm1f(sa.w);
        }
        As[ak + 0][ar] = sa.x;
        As[ak + 1][ar] = sa.y;
        As[ak + 2][ar] = sa.z;
        As[ak + 3][ar] = sa.w;
        if (doB) *(float4*)&Bs[br][bc] = pb;
        __syncthreads();

        // prefetch next tiles (hidden behind the FMA loop)
        if (k0 + BK < K) {
            if (agr < M) pa = *(const float4*)&A[(size_t)agr * K + (k0 + BK) + ak];
            if (doB)     pb = *(const float4*)&B[(size_t)(k0 + BK + br) * N + colBase + bc];
        }

#pragma unroll
        for (int k = 0; k < BK; k++) {
            float a[TM], b[TN];
#pragma unroll
            for (int i = 0; i < TM; i++) a[i] = As[k][trow * TM + i];
#pragma unroll
            for (int j = 0; j < TN; j++) b[j] = Bs[k][tcol * TN + j];
#pragma unroll
            for (int i = 0; i < TM; i++)
#pragma unroll
                for (int j = 0; j < TN; j++) acc[i][j] += a[i] * b[j];
        }
        __syncthreads();
    }
#pragma unroll
    for (int i = 0; i < TM; i++) {
        int gr = rowBase + trow * TM + i;
        if (gr >= M) continue;
        float* cp = &C[(size_t)gr * N + colBase + tcol * TN];
#pragma unroll
        for (int j = 0; j < TN; j += 4)
            *(float4*)&cp[j] = make_float4(acc[i][j], acc[i][j+1], acc[i][j+2], acc[i][j+3]);
    }
}

// ---------------- per-node attention halves ----------------
__global__ void attn_lr1(const float* __restrict__ al, const float* __restrict__ ar) {
    int i = blockIdx.x * blockDim.x + threadIdx.x;   // over NN*HEADS
    if (i >= NN * HEADS) return;
    int h = i & (HEADS - 1);
    const float4* fp = (const float4*)(g_f1 + (size_t)(i >> 3) * F1DIM + h * HID);
    const float4* alp = (const float4*)(al + h * HID);
    const float4* arp = (const float4*)(ar + h * HID);
    float sl = 0.f, sr = 0.f;
#pragma unroll
    for (int q = 0; q < 8; q++) {
        float4 v = fp[q], a = alp[q], b = arp[q];
        sl += v.x * a.x + v.y * a.y + v.z * a.z + v.w * a.w;
        sr += v.x * b.x + v.y * b.y + v.z * b.z + v.w * b.w;
    }
    g_el1[i] = sl;
    g_er1[i] = sr;
}

__global__ void attn_lr2(const float* __restrict__ al, const float* __restrict__ ar) {
    int i = blockIdx.x * blockDim.x + threadIdx.x;   // over NN
    if (i >= NN) return;
    const float4* fp = (const float4*)(g_f2 + (size_t)i * ODIM);
    const float4* alp = (const float4*)al;
    const float4* arp = (const float4*)ar;
    float sl = 0.f, sr = 0.f;
#pragma unroll
    for (int q = 0; q < 16; q++) {
        float4 v = fp[q], a = alp[q], b = arp[q];
        sl += v.x * a.x + v.y * a.y + v.z * a.z + v.w * a.w;
        sr += v.x * b.x + v.y * b.y + v.z * b.z + v.w * b.w;
    }
    g_el2[i] = sl;
    g_er2[i] = sr;
}

// ---------------- layer-1 aggregation: one warp per dst node, SINGLE PASS --------------
// lane owns output floats [lane*8, lane*8+8); head = lane>>2.
// out = (sum_e a_e * f_src) * (1/sum_e a_e) + b1
__global__ void __launch_bounds__(256)
agg1(const float* __restrict__ b1) {
    int warp = (blockIdx.x * blockDim.x + threadIdx.x) >> 5;
    if (warp >= NN) return;
    const int lane = threadIdx.x & 31;
    const int node = warp;
    const int h4 = lane >> 2;
    const int beg = g_off[node], end = g_off[node + 1];

    const float er = g_er1[node * HEADS + h4];

    float acc[8];
#pragma unroll
    for (int j = 0; j < 8; j++) acc[j] = 0.f;
    float ssum = 0.f;

    int i = beg;
    for (; i + 2 <= end; i += 2) {
        int s0 = g_psrc[i], s1 = g_psrc[i + 1];
        float a0 = __expf(lrelu(g_el1[s0 * HEADS + h4] + er));
        float a1 = __expf(lrelu(g_el1[s1 * HEADS + h4] + er));
        const float4* f0 = (const float4*)&g_f1[(size_t)s0 * F1DIM + lane * 8];
        const float4* f1 = (const float4*)&g_f1[(size_t)s1 * F1DIM + lane * 8];
        float4 u0 = f0[0], u1 = f0[1];
        float4 w0 = f1[0], w1 = f1[1];
        ssum += a0 + a1;
        acc[0] += a0 * u0.x + a1 * w0.x;  acc[1] += a0 * u0.y + a1 * w0.y;
        acc[2] += a0 * u0.z + a1 * w0.z;  acc[3] += a0 * u0.w + a1 * w0.w;
        acc[4] += a0 * u1.x + a1 * w1.x;  acc[5] += a0 * u1.y + a1 * w1.y;
        acc[6] += a0 * u1.z + a1 * w1.z;  acc[7] += a0 * u1.w + a1 * w1.w;
    }
    if (i < end) {
        int s0 = g_psrc[i];
        float a0 = __expf(lrelu(g_el1[s0 * HEADS + h4] + er));
        const float4* f0 = (const float4*)&g_f1[(size_t)s0 * F1DIM + lane * 8];
        float4 u0 = f0[0], u1 = f0[1];
        ssum += a0;
        acc[0] += a0 * u0.x;  acc[1] += a0 * u0.y;
        acc[2] += a0 * u0.z;  acc[3] += a0 * u0.w;
        acc[4] += a0 * u1.x;  acc[5] += a0 * u1.y;
        acc[6] += a0 * u1.z;  acc[7] += a0 * u1.w;
    }

    const float inv = ssum > 0.f ? 1.f / ssum : 0.f;   // isolated node -> acc==0, avoid NaN
    const float4* bp = (const float4*)&b1[lane * 8];
    float4 bb0 = bp[0], bb1 = bp[1];
    float4* op = (float4*)&g_h[(size_t)node * F1DIM + lane * 8];
    op[0] = make_float4(acc[0] * inv + bb0.x, acc[1] * inv + bb0.y,
                        acc[2] * inv + bb0.z, acc[3] * inv + bb0.w);
    op[1] = make_float4(acc[4] * inv + bb1.x, acc[5] * inv + bb1.y,
                        acc[6] * inv + bb1.z, acc[7] * inv + bb1.w);
}

// ---------------- layer-2 aggregation: one warp per dst node, SINGLE PASS --------------
// lane owns output floats [lane*2, lane*2+2).
__global__ void __launch_bounds__(256)
agg2(float* __restrict__ out, const float* __restrict__ b2) {
    int warp = (blockIdx.x * blockDim.x + threadIdx.x) >> 5;
    if (warp >= NN) return;
    const int lane = threadIdx.x & 31;
    const int node = warp;
    const int beg = g_off[node], end = g_off[node + 1];

    const float er = g_er2[node];

    float a0 = 0.f, a1 = 0.f, ssum = 0.f;
    int i = beg;
    for (; i + 4 <= end; i += 4) {
        int s0 = g_psrc[i], s1 = g_psrc[i+1], s2 = g_psrc[i+2], s3 = g_psrc[i+3];
        float e0 = __expf(lrelu(g_el2[s0] + er));
        float e1 = __expf(lrelu(g_el2[s1] + er));
        float e2 = __expf(lrelu(g_el2[s2] + er));
        float e3 = __expf(lrelu(g_el2[s3] + er));
        float2 v0 = *(const float2*)&g_f2[(size_t)s0 * ODIM + lane * 2];
        float2 v1 = *(const float2*)&g_f2[(size_t)s1 * ODIM + lane * 2];
        float2 v2 = *(const float2*)&g_f2[(size_t)s2 * ODIM + lane * 2];
        float2 v3 = *(const float2*)&g_f2[(size_t)s3 * ODIM + lane * 2];
        ssum += (e0 + e1) + (e2 + e3);
        a0 += e0 * v0.x + e1 * v1.x + e2 * v2.x + e3 * v3.x;
        a1 += e0 * v0.y + e1 * v1.y + e2 * v2.y + e3 * v3.y;
    }
    for (; i < end; i++) {
        int s = g_psrc[i];
        float e0 = __expf(lrelu(g_el2[s] + er));
        float2 v = *(const float2*)&g_f2[(size_t)s * ODIM + lane * 2];
        ssum += e0;
        a0 += e0 * v.x;
        a1 += e0 * v.y;
    }
    const float inv = ssum > 0.f ? 1.f / ssum : 0.f;
    float2 bb = *(const float2*)&b2[lane * 2];
    *(float2*)&out[(size_t)node * ODIM + lane * 2] = make_float2(a0 * inv + bb.x, a1 * inv + bb.y);
}

// ---------------- launch ----------------
extern "C" void kernel_launch(void* const* d_in, const int* in_sizes, int n_in,
                              void* d_out, int out_size) {
    const float* feat = (const float*)d_in[0];
    const int*   src  = (const int*)  d_in[1];
    const int*   dst  = (const int*)  d_in[2];
    const float* W1   = (const float*)d_in[3];
    const float* al1  = (const float*)d_in[4];
    const float* ar1  = (const float*)d_in[5];
    const float* b1   = (const float*)d_in[6];
    const float* W2   = (const float*)d_in[7];
    const float* al2  = (const float*)d_in[8];
    const float* ar2  = (const float*)d_in[9];
    const float* b2   = (const float*)d_in[10];
    float* out = (float*)d_out;

    float *pf1, *ph, *pf2;
    cudaGetSymbolAddress((void**)&pf1, g_f1);
    cudaGetSymbolAddress((void**)&ph,  g_h);
    cudaGetSymbolAddress((void**)&pf2, g_f2);

    const int T = 256;
    auto cdiv = [](long long a, long long b) { return (int)((a + b - 1) / b); };

    // CSR build (shared by both layers)
    zero_cnt<<<cdiv(NN, T), T>>>();
    count_dst<<<cdiv(NE, T), T>>>(dst);
    scan_off<<<1, 1024>>>();
    place_edges<<<cdiv(NE, T), T>>>(src, dst);

    // Layer 1
    gemm_kernel<128,128,8,8,8,false><<<dim3(F1DIM/128, cdiv(NN,128)), 256>>>(feat, W1, pf1, NN, F1DIM, IN_DIM);
    attn_lr1<<<cdiv(NN*HEADS, T), T>>>(al1, ar1);
    agg1<<<cdiv((long long)NN*32, T), T>>>(b1);

    // Layer 2 (ELU fused into GEMM2's A-tile load)
    gemm_kernel<128,64,8,8,4,true><<<dim3(ODIM/64, cdiv(NN,128)), 256>>>(ph, W2, pf2, NN, ODIM, F1DIM);
    attn_lr2<<<cdiv(NN, T), T>>>(al2, ar2);
    agg2<<<cdiv((long long)NN*32, T), T>>>(out, b2);
}

// round 10
// speedup vs baseline: 2.0156x; 1.0826x over previous
#include <cuda_runtime.h>
#include <cuda_fp16.h>
#include <math.h>

#define NN 50000
#define NE 800000
#define IN_DIM 128
#define HID 32
#define HEADS 8
#define F1DIM 256
#define ODIM 64
#define NEG 0.2f
#define FULL 0xffffffffu

// ---------------- scratch (device globals; no allocation) ----------------
__device__ alignas(16) float  g_f1 [(size_t)NN * F1DIM];   // 51.2 MB
__device__ alignas(16) __half g_f1h[(size_t)NN * F1DIM];   // 25.6 MB (fp16 gather table)
__device__ alignas(16) float  g_h  [(size_t)NN * F1DIM];   // 51.2 MB
__device__ alignas(16) float  g_f2 [(size_t)NN * ODIM];    // 12.8 MB
__device__ alignas(16) __half g_f2h[(size_t)NN * ODIM];    // 6.4 MB
__device__ float g_el1[NN * HEADS];
__device__ float g_er1[NN * HEADS];
__device__ float g_el2[NN];
__device__ float g_er2[NN];
// CSR (dst-sorted), built on device each call
__device__ int g_cnt [NN];
__device__ int g_off [NN + 1];
__device__ int g_pos [NN];
__device__ int g_psrc[NE];

__device__ __forceinline__ float lrelu(float x) { return x >= 0.f ? x : NEG * x; }

// ---------------- CSR build ----------------
__global__ void zero_cnt() {
    int i = blockIdx.x * blockDim.x + threadIdx.x;
    if (i < NN) g_cnt[i] = 0;
}
__global__ void count_dst(const int* __restrict__ dst) {
    int e = blockIdx.x * blockDim.x + threadIdx.x;
    if (e < NE) atomicAdd(&g_cnt[dst[e]], 1);
}
__global__ void scan_off() {
    __shared__ int wsum[32];
    const int t = threadIdx.x;
    const int C = (NN + 1023) / 1024;
    const int base = t * C;
    int s = 0;
    for (int j = 0; j < C; j++) { int idx = base + j; if (idx < NN) s += g_cnt[idx]; }
    int lane = t & 31, wid = t >> 5;
    int v = s;
#pragma unroll
    for (int o = 1; o < 32; o <<= 1) { int n = __shfl_up_sync(FULL, v, o); if (lane >= o) v += n; }
    if (lane == 31) wsum[wid] = v;
    __syncthreads();
    if (wid == 0) {
        int w = wsum[lane];
#pragma unroll
        for (int o = 1; o < 32; o <<= 1) { int n = __shfl_up_sync(FULL, w, o); if (lane >= o) w += n; }
        wsum[lane] = w;
    }
    __syncthreads();
    int run = (v - s) + (wid > 0 ? wsum[wid - 1] : 0);
    for (int j = 0; j < C; j++) {
        int idx = base + j;
        if (idx < NN) { g_off[idx] = run; g_pos[idx] = run; run += g_cnt[idx]; }
    }
    if (t == 1023) g_off[NN] = NE;
}
__global__ void place_edges(const int* __restrict__ src, const int* __restrict__ dst) {
    int e = blockIdx.x * blockDim.x + threadIdx.x;
    if (e >= NE) return;
    int slot = atomicAdd(&g_pos[dst[e]], 1);
    g_psrc[slot] = src[e];
}

// ---------------- GEMM: C[M,N] = A[M,K] @ B[K,N], row-major, BK=16, reg-prefetch ------
template<int BM, int BN, int BK, int TM, int TN, bool ELUA>
__global__ void __launch_bounds__(256, 2)
gemm_kernel(const float* __restrict__ A, const float* __restrict__ B,
            float* __restrict__ C, int M, int N, int K) {
    __shared__ float As[BK][BM];
    __shared__ float Bs[BK][BN];
    constexpr int AL = (BM * BK) / 1024;   // float4 A-loads per thread
    constexpr int BL = (BK * BN) / 1024;   // float4 B-loads per thread
    const int tid  = threadIdx.x;
    const int tcol = tid % (BN / TN);
    const int trow = tid / (BN / TN);
    const int rowBase = blockIdx.y * BM;
    const int colBase = blockIdx.x * BN;

    int arow[AL], akk[AL];
#pragma unroll
    for (int l = 0; l < AL; l++) {
        int f = (tid + l * 256) * 4;
        arow[l] = f / BK; akk[l] = f % BK;
    }
    int brow[BL], bcc[BL];
#pragma unroll
    for (int l = 0; l < BL; l++) {
        int f = (tid + l * 256) * 4;
        brow[l] = f / BN; bcc[l] = f % BN;
    }

    float acc[TM][TN];
#pragma unroll
    for (int i = 0; i < TM; i++)
#pragma unroll
        for (int j = 0; j < TN; j++) acc[i][j] = 0.f;

    float4 pa[AL], pb[BL];
#pragma unroll
    for (int l = 0; l < AL; l++) {
        pa[l] = make_float4(0.f, 0.f, 0.f, 0.f);
        if (rowBase + arow[l] < M) pa[l] = *(const float4*)&A[(size_t)(rowBase + arow[l]) * K + akk[l]];
    }
#pragma unroll
    for (int l = 0; l < BL; l++)
        pb[l] = *(const float4*)&B[(size_t)brow[l] * N + colBase + bcc[l]];

    for (int k0 = 0; k0 < K; k0 += BK) {
#pragma unroll
        for (int l = 0; l < AL; l++) {
            float4 sa = pa[l];
            if (ELUA) {
                sa.x = sa.x > 0.f ? sa.x : expm1f(sa.x);
                sa.y = sa.y > 0.f ? sa.y : expm1f(sa.y);
                sa.z = sa.z > 0.f ? sa.z : expm1f(sa.z);
                sa.w = sa.w > 0.f ? sa.w : expm1f(sa.w);
            }
            As[akk[l] + 0][arow[l]] = sa.x;
            As[akk[l] + 1][arow[l]] = sa.y;
            As[akk[l] + 2][arow[l]] = sa.z;
            As[akk[l] + 3][arow[l]] = sa.w;
        }
#pragma unroll
        for (int l = 0; l < BL; l++)
            *(float4*)&Bs[brow[l]][bcc[l]] = pb[l];
        __syncthreads();

        if (k0 + BK < K) {
#pragma unroll
            for (int l = 0; l < AL; l++)
                if (rowBase + arow[l] < M)
                    pa[l] = *(const float4*)&A[(size_t)(rowBase + arow[l]) * K + (k0 + BK) + akk[l]];
#pragma unroll
            for (int l = 0; l < BL; l++)
                pb[l] = *(const float4*)&B[(size_t)(k0 + BK + brow[l]) * N + colBase + bcc[l]];
        }

#pragma unroll
        for (int k = 0; k < BK; k++) {
            float a[TM], b[TN];
#pragma unroll
            for (int i = 0; i < TM; i++) a[i] = As[k][trow * TM + i];
#pragma unroll
            for (int j = 0; j < TN; j++) b[j] = Bs[k][tcol * TN + j];
#pragma unroll
            for (int i = 0; i < TM; i++)
#pragma unroll
                for (int j = 0; j < TN; j++) acc[i][j] += a[i] * b[j];
        }
        __syncthreads();
    }
#pragma unroll
    for (int i = 0; i < TM; i++) {
        int gr = rowBase + trow * TM + i;
        if (gr >= M) continue;
        float* cp = &C[(size_t)gr * N + colBase + tcol * TN];
#pragma unroll
        for (int j = 0; j < TN; j += 4)
            *(float4*)&cp[j] = make_float4(acc[i][j], acc[i][j+1], acc[i][j+2], acc[i][j+3]);
    }
}

// ---------------- per-node attention halves (+ fp16 table conversion) ----------------
__global__ void attn_lr1(const float* __restrict__ al, const float* __restrict__ ar) {
    int i = blockIdx.x * blockDim.x + threadIdx.x;   // over NN*HEADS
    if (i >= NN * HEADS) return;
    int h = i & (HEADS - 1);
    const size_t base = (size_t)(i >> 3) * F1DIM + h * HID;
    const float4* fp = (const float4*)(g_f1 + base);
    const float4* alp = (const float4*)(al + h * HID);
    const float4* arp = (const float4*)(ar + h * HID);
    float sl = 0.f, sr = 0.f;
#pragma unroll
    for (int q = 0; q < 8; q++) {
        float4 v = fp[q], a = alp[q], b = arp[q];
        sl += v.x * a.x + v.y * a.y + v.z * a.z + v.w * a.w;
        sr += v.x * b.x + v.y * b.y + v.z * b.z + v.w * b.w;
        // fp16 conversion (message table for agg1)
        __half2 h0 = __floats2half2_rn(v.x, v.y);
        __half2 h1 = __floats2half2_rn(v.z, v.w);
        *(uint2*)&g_f1h[base + q * 4] = make_uint2(*(unsigned*)&h0, *(unsigned*)&h1);
    }
    g_el1[i] = sl;
    g_er1[i] = sr;
}

__global__ void attn_lr2(const float* __restrict__ al, const float* __restrict__ ar) {
    int i = blockIdx.x * blockDim.x + threadIdx.x;   // over NN
    if (i >= NN) return;
    const size_t base = (size_t)i * ODIM;
    const float4* fp = (const float4*)(g_f2 + base);
    const float4* alp = (const float4*)al;
    const float4* arp = (const float4*)ar;
    float sl = 0.f, sr = 0.f;
#pragma unroll
    for (int q = 0; q < 16; q++) {
        float4 v = fp[q], a = alp[q], b = arp[q];
        sl += v.x * a.x + v.y * a.y + v.z * a.z + v.w * a.w;
        sr += v.x * b.x + v.y * b.y + v.z * b.z + v.w * b.w;
        __half2 h0 = __floats2half2_rn(v.x, v.y);
        __half2 h1 = __floats2half2_rn(v.z, v.w);
        *(uint2*)&g_f2h[base + q * 4] = make_uint2(*(unsigned*)&h0, *(unsigned*)&h1);
    }
    g_el2[i] = sl;
    g_er2[i] = sr;
}

// ---------------- layer-1 aggregation: warp/node, single pass, fp16 gather ----------
// lane owns output floats [lane*8, lane*8+8); head = lane>>2. Gather = one uint4/lane.
__global__ void __launch_bounds__(256)
agg1(const float* __restrict__ b1) {
    int warp = (blockIdx.x * blockDim.x + threadIdx.x) >> 5;
    if (warp >= NN) return;
    const int lane = threadIdx.x & 31;
    const int node = warp;
    const int h4 = lane >> 2;
    const int beg = g_off[node], end = g_off[node + 1];

    const float er = g_er1[node * HEADS + h4];

    float acc[8];
#pragma unroll
    for (int j = 0; j < 8; j++) acc[j] = 0.f;
    float ssum = 0.f;

    int i = beg;
    for (; i + 2 <= end; i += 2) {
        int s0 = g_psrc[i], s1 = g_psrc[i + 1];
        float a0 = __expf(lrelu(g_el1[s0 * HEADS + h4] + er));
        float a1 = __expf(lrelu(g_el1[s1 * HEADS + h4] + er));
        uint4 u0 = *(const uint4*)&g_f1h[(size_t)s0 * F1DIM + lane * 8];
        uint4 u1 = *(const uint4*)&g_f1h[(size_t)s1 * F1DIM + lane * 8];
        ssum += a0 + a1;
        const __half2* p0 = (const __half2*)&u0;
        const __half2* p1 = (const __half2*)&u1;
#pragma unroll
        for (int j = 0; j < 4; j++) {
            float2 f0 = __half22float2(p0[j]);
            float2 f1 = __half22float2(p1[j]);
            acc[2*j + 0] += a0 * f0.x + a1 * f1.x;
            acc[2*j + 1] += a0 * f0.y + a1 * f1.y;
        }
    }
    if (i < end) {
        int s0 = g_psrc[i];
        float a0 = __expf(lrelu(g_el1[s0 * HEADS + h4] + er));
        uint4 u0 = *(const uint4*)&g_f1h[(size_t)s0 * F1DIM + lane * 8];
        ssum += a0;
        const __half2* p0 = (const __half2*)&u0;
#pragma unroll
        for (int j = 0; j < 4; j++) {
            float2 f0 = __half22float2(p0[j]);
            acc[2*j + 0] += a0 * f0.x;
            acc[2*j + 1] += a0 * f0.y;
        }
    }

    const float inv = ssum > 0.f ? 1.f / ssum : 0.f;
    const float4* bp = (const float4*)&b1[lane * 8];
    float4 bb0 = bp[0], bb1 = bp[1];
    float4* op = (float4*)&g_h[(size_t)node * F1DIM + lane * 8];
    op[0] = make_float4(acc[0] * inv + bb0.x, acc[1] * inv + bb0.y,
                        acc[2] * inv + bb0.z, acc[3] * inv + bb0.w);
    op[1] = make_float4(acc[4] * inv + bb1.x, acc[5] * inv + bb1.y,
                        acc[6] * inv + bb1.z, acc[7] * inv + bb1.w);
}

// ---------------- layer-2 aggregation: warp/node, single pass, fp16 gather ----------
// lane owns output floats [lane*2, lane*2+2). Gather = one half2 (4B)/lane.
__global__ void __launch_bounds__(256)
agg2(float* __restrict__ out, const float* __restrict__ b2) {
    int warp = (blockIdx.x * blockDim.x + threadIdx.x) >> 5;
    if (warp >= NN) return;
    const int lane = threadIdx.x & 31;
    const int node = warp;
    const int beg = g_off[node], end = g_off[node + 1];

    const float er = g_er2[node];

    float a0 = 0.f, a1 = 0.f, ssum = 0.f;
    int i = beg;
    for (; i + 4 <= end; i += 4) {
        int s0 = g_psrc[i], s1 = g_psrc[i+1], s2 = g_psrc[i+2], s3 = g_psrc[i+3];
        float e0 = __expf(lrelu(g_el2[s0] + er));
        float e1 = __expf(lrelu(g_el2[s1] + er));
        float e2 = __expf(lrelu(g_el2[s2] + er));
        float e3 = __expf(lrelu(g_el2[s3] + er));
        float2 v0 = __half22float2(*(const __half2*)&g_f2h[(size_t)s0 * ODIM + lane * 2]);
        float2 v1 = __half22float2(*(const __half2*)&g_f2h[(size_t)s1 * ODIM + lane * 2]);
        float2 v2 = __half22float2(*(const __half2*)&g_f2h[(size_t)s2 * ODIM + lane * 2]);
        float2 v3 = __half22float2(*(const __half2*)&g_f2h[(size_t)s3 * ODIM + lane * 2]);
        ssum += (e0 + e1) + (e2 + e3);
        a0 += e0 * v0.x + e1 * v1.x + e2 * v2.x + e3 * v3.x;
        a1 += e0 * v0.y + e1 * v1.y + e2 * v2.y + e3 * v3.y;
    }
    for (; i < end; i++) {
        int s = g_psrc[i];
        float e0 = __expf(lrelu(g_el2[s] + er));
        float2 v = __half22float2(*(const __half2*)&g_f2h[(size_t)s * ODIM + lane * 2]);
        ssum += e0;
        a0 += e0 * v.x;
        a1 += e0 * v.y;
    }
    const float inv = ssum > 0.f ? 1.f / ssum : 0.f;
    float2 bb = *(const float2*)&b2[lane * 2];
    *(float2*)&out[(size_t)node * ODIM + lane * 2] = make_float2(a0 * inv + bb.x, a1 * inv + bb.y);
}

// ---------------- launch ----------------
extern "C" void kernel_launch(void* const* d_in, const int* in_sizes, int n_in,
                              void* d_out, int out_size) {
    const float* feat = (const float*)d_in[0];
    const int*   src  = (const int*)  d_in[1];
    const int*   dst  = (const int*)  d_in[2];
    const float* W1   = (const float*)d_in[3];
    const float* al1  = (const float*)d_in[4];
    const float* ar1  = (const float*)d_in[5];
    const float* b1   = (const float*)d_in[6];
    const float* W2   = (const float*)d_in[7];
    const float* al2  = (const float*)d_in[8];
    const float* ar2  = (const float*)d_in[9];
    const float* b2   = (const float*)d_in[10];
    float* out = (float*)d_out;

    float *pf1, *ph, *pf2;
    cudaGetSymbolAddress((void**)&pf1, g_f1);
    cudaGetSymbolAddress((void**)&ph,  g_h);
    cudaGetSymbolAddress((void**)&pf2, g_f2);

    const int T = 256;
    auto cdiv = [](long long a, long long b) { return (int)((a + b - 1) / b); };

    // CSR build (shared by both layers)
    zero_cnt<<<cdiv(NN, T), T>>>();
    count_dst<<<cdiv(NE, T), T>>>(dst);
    scan_off<<<1, 1024>>>();
    place_edges<<<cdiv(NE, T), T>>>(src, dst);

    // Layer 1
    gemm_kernel<128,128,16,8,8,false><<<dim3(F1DIM/128, cdiv(NN,128)), 256>>>(feat, W1, pf1, NN, F1DIM, IN_DIM);
    attn_lr1<<<cdiv(NN*HEADS, T), T>>>(al1, ar1);
    agg1<<<cdiv((long long)NN*32, T), T>>>(b1);

    // Layer 2 (ELU fused into GEMM2's A-tile load)
    gemm_kernel<128,64,16,8,4,true><<<dim3(ODIM/64, cdiv(NN,128)), 256>>>(ph, W2, pf2, NN, ODIM, F1DIM);
    attn_lr2<<<cdiv(NN, T), T>>>(al2, ar2);
    agg2<<<cdiv((long long)NN*32, T), T>>>(out, b2);
}

// round 11
// speedup vs baseline: 2.1844x; 1.0837x over previous
#include <cuda_runtime.h>
#include <cuda_fp16.h>
#include <mma.h>
#include <math.h>

using namespace nvcuda;

#define NN 50000
#define NNP 50048            // padded rows for unguarded wmma stores
#define NE 800000
#define IN_DIM 128
#define HID 32
#define HEADS 8
#define F1DIM 256
#define ODIM 64
#define NEG 0.2f
#define FULL 0xffffffffu

// ---------------- scratch (device globals; no allocation) ----------------
__device__ alignas(16) float  g_f1 [(size_t)NNP * F1DIM];
__device__ alignas(16) __half g_f1h[(size_t)NN  * F1DIM];
__device__ alignas(16) float  g_h  [(size_t)NNP * F1DIM];   // zero-init; padded rows stay 0
__device__ alignas(16) float  g_f2 [(size_t)NNP * ODIM];
__device__ alignas(16) __half g_f2h[(size_t)NN  * ODIM];
__device__ float g_el1[NN * HEADS];
__device__ float g_er1[NN * HEADS];
__device__ float g_el2[NN];
__device__ float g_er2[NN];
__device__ int g_cnt [NN];
__device__ int g_off [NN + 1];
__device__ int g_pos [NN];
__device__ int g_psrc[NE];

__device__ __forceinline__ float lrelu(float x) { return x >= 0.f ? x : NEG * x; }

// ---------------- CSR build ----------------
__global__ void zero_cnt() {
    int i = blockIdx.x * blockDim.x + threadIdx.x;
    if (i < NN) g_cnt[i] = 0;
}
__global__ void count_dst(const int* __restrict__ dst) {
    int e = blockIdx.x * blockDim.x + threadIdx.x;
    if (e < NE) atomicAdd(&g_cnt[dst[e]], 1);
}
__global__ void scan_off() {
    __shared__ int wsum[32];
    const int t = threadIdx.x;
    const int C = (NN + 1023) / 1024;
    const int base = t * C;
    int s = 0;
    for (int j = 0; j < C; j++) { int idx = base + j; if (idx < NN) s += g_cnt[idx]; }
    int lane = t & 31, wid = t >> 5;
    int v = s;
#pragma unroll
    for (int o = 1; o < 32; o <<= 1) { int n = __shfl_up_sync(FULL, v, o); if (lane >= o) v += n; }
    if (lane == 31) wsum[wid] = v;
    __syncthreads();
    if (wid == 0) {
        int w = wsum[lane];
#pragma unroll
        for (int o = 1; o < 32; o <<= 1) { int n = __shfl_up_sync(FULL, w, o); if (lane >= o) w += n; }
        wsum[lane] = w;
    }
    __syncthreads();
    int run = (v - s) + (wid > 0 ? wsum[wid - 1] : 0);
    for (int j = 0; j < C; j++) {
        int idx = base + j;
        if (idx < NN) { g_off[idx] = run; g_pos[idx] = run; run += g_cnt[idx]; }
    }
    if (t == 1023) g_off[NN] = NE;
}
__global__ void place_edges(const int* __restrict__ src, const int* __restrict__ dst) {
    int e = blockIdx.x * blockDim.x + threadIdx.x;
    if (e >= NE) return;
    int slot = atomicAdd(&g_pos[dst[e]], 1);
    g_psrc[slot] = src[e];
}

// ---------------- tf32 tensor-core GEMM ----------------
// C[M_pad,N] = A[M,K] @ B[K,N]; BM=128 BN=64 BK=32; 8 warps, warp tile 32x32.
// A loads guarded by M (real rows); C stores unguarded (padded scratch).
#define LDA 40
#define LDB 72
template<bool ELUA>
__global__ void __launch_bounds__(256, 2)
gemm_tf32(const float* __restrict__ A, const float* __restrict__ B,
          float* __restrict__ C, int M, int N, int K) {
    __shared__ float As[128 * LDA];
    __shared__ float Bs[32 * LDB];
    const int tid = threadIdx.x;
    const int wid = tid >> 5;
    const int wm = (wid & 3) * 32;          // warp M offset (4 warps in M)
    const int wn = (wid >> 2) * 32;         // warp N offset (2 warps in N)
    const int rowBase = blockIdx.y * 128;
    const int colBase = blockIdx.x * 64;

    // per-thread load coords
    int aRow[4], aK[4];
#pragma unroll
    for (int l = 0; l < 4; l++) {
        int f = tid + l * 256;              // float4 index in 128x32 tile
        aRow[l] = f >> 3; aK[l] = (f & 7) * 4;
    }
    int bRow[2], bCol[2];
#pragma unroll
    for (int l = 0; l < 2; l++) {
        int f = tid + l * 256;              // float4 index in 32x64 tile
        bRow[l] = f >> 4; bCol[l] = (f & 15) * 4;
    }

    wmma::fragment<wmma::accumulator, 16, 16, 8, float> acc[2][2];
#pragma unroll
    for (int i = 0; i < 2; i++)
#pragma unroll
        for (int j = 0; j < 2; j++) wmma::fill_fragment(acc[i][j], 0.f);

    float4 pa[4], pb[2];
#pragma unroll
    for (int l = 0; l < 4; l++) {
        pa[l] = make_float4(0.f, 0.f, 0.f, 0.f);
        if (rowBase + aRow[l] < M) pa[l] = *(const float4*)&A[(size_t)(rowBase + aRow[l]) * K + aK[l]];
    }
#pragma unroll
    for (int l = 0; l < 2; l++)
        pb[l] = *(const float4*)&B[(size_t)bRow[l] * N + colBase + bCol[l]];

    for (int k0 = 0; k0 < K; k0 += 32) {
#pragma unroll
        for (int l = 0; l < 4; l++) {
            float4 sa = pa[l];
            if (ELUA) {
                sa.x = sa.x > 0.f ? sa.x : expm1f(sa.x);
                sa.y = sa.y > 0.f ? sa.y : expm1f(sa.y);
                sa.z = sa.z > 0.f ? sa.z : expm1f(sa.z);
                sa.w = sa.w > 0.f ? sa.w : expm1f(sa.w);
            }
            float* p = &As[aRow[l] * LDA + aK[l]];
            p[0] = sa.x; p[1] = sa.y; p[2] = sa.z; p[3] = sa.w;
        }
#pragma unroll
        for (int l = 0; l < 2; l++) {
            float* p = &Bs[bRow[l] * LDB + bCol[l]];
            p[0] = pb[l].x; p[1] = pb[l].y; p[2] = pb[l].z; p[3] = pb[l].w;
        }
        __syncthreads();

        if (k0 + 32 < K) {
#pragma unroll
            for (int l = 0; l < 4; l++)
                if (rowBase + aRow[l] < M)
                    pa[l] = *(const float4*)&A[(size_t)(rowBase + aRow[l]) * K + (k0 + 32) + aK[l]];
#pragma unroll
            for (int l = 0; l < 2; l++)
                pb[l] = *(const float4*)&B[(size_t)(k0 + 32 + bRow[l]) * N + colBase + bCol[l]];
        }

#pragma unroll
        for (int kk = 0; kk < 32; kk += 8) {
            wmma::fragment<wmma::matrix_a, 16, 16, 8, wmma::precision::tf32, wmma::row_major> af[2];
            wmma::fragment<wmma::matrix_b, 16, 16, 8, wmma::precision::tf32, wmma::row_major> bf[2];
#pragma unroll
            for (int i = 0; i < 2; i++) {
                wmma::load_matrix_sync(af[i], &As[(wm + i * 16) * LDA + kk], LDA);
#pragma unroll
                for (int t = 0; t < af[i].num_elements; t++)
                    af[i].x[t] = wmma::__float_to_tf32(af[i].x[t]);
            }
#pragma unroll
            for (int j = 0; j < 2; j++) {
                wmma::load_matrix_sync(bf[j], &Bs[kk * LDB + wn + j * 16], LDB);
#pragma unroll
                for (int t = 0; t < bf[j].num_elements; t++)
                    bf[j].x[t] = wmma::__float_to_tf32(bf[j].x[t]);
            }
#pragma unroll
            for (int i = 0; i < 2; i++)
#pragma unroll
                for (int j = 0; j < 2; j++)
                    wmma::mma_sync(acc[i][j], af[i], bf[j], acc[i][j]);
        }
        __syncthreads();
    }

#pragma unroll
    for (int i = 0; i < 2; i++)
#pragma unroll
        for (int j = 0; j < 2; j++)
            wmma::store_matrix_sync(&C[(size_t)(rowBase + wm + i * 16) * N + colBase + wn + j * 16],
                                    acc[i][j], N, wmma::mem_row_major);
}

// ---------------- per-node attention halves (+ fp16 table conversion) ----------------
__global__ void attn_lr1(const float* __restrict__ al, const float* __restrict__ ar) {
    int i = blockIdx.x * blockDim.x + threadIdx.x;
    if (i >= NN * HEADS) return;
    int h = i & (HEADS - 1);
    const size_t base = (size_t)(i >> 3) * F1DIM + h * HID;
    const float4* fp = (const float4*)(g_f1 + base);
    const float4* alp = (const float4*)(al + h * HID);
    const float4* arp = (const float4*)(ar + h * HID);
    float sl = 0.f, sr = 0.f;
#pragma unroll
    for (int q = 0; q < 8; q++) {
        float4 v = fp[q], a = alp[q], b = arp[q];
        sl += v.x * a.x + v.y * a.y + v.z * a.z + v.w * a.w;
        sr += v.x * b.x + v.y * b.y + v.z * b.z + v.w * b.w;
        __half2 h0 = __floats2half2_rn(v.x, v.y);
        __half2 h1 = __floats2half2_rn(v.z, v.w);
        *(uint2*)&g_f1h[base + q * 4] = make_uint2(*(unsigned*)&h0, *(unsigned*)&h1);
    }
    g_el1[i] = sl;
    g_er1[i] = sr;
}

__global__ void attn_lr2(const float* __restrict__ al, const float* __restrict__ ar) {
    int i = blockIdx.x * blockDim.x + threadIdx.x;
    if (i >= NN) return;
    const size_t base = (size_t)i * ODIM;
    const float4* fp = (const float4*)(g_f2 + base);
    const float4* alp = (const float4*)al;
    const float4* arp = (const float4*)ar;
    float sl = 0.f, sr = 0.f;
#pragma unroll
    for (int q = 0; q < 16; q++) {
        float4 v = fp[q], a = alp[q], b = arp[q];
        sl += v.x * a.x + v.y * a.y + v.z * a.z + v.w * a.w;
        sr += v.x * b.x + v.y * b.y + v.z * b.z + v.w * b.w;
        __half2 h0 = __floats2half2_rn(v.x, v.y);
        __half2 h1 = __floats2half2_rn(v.z, v.w);
        *(uint2*)&g_f2h[base + q * 4] = make_uint2(*(unsigned*)&h0, *(unsigned*)&h1);
    }
    g_el2[i] = sl;
    g_er2[i] = sr;
}

// ---------------- layer-1 aggregation: warp/node, single pass, fp16 gather ----------
__global__ void __launch_bounds__(256)
agg1(const float* __restrict__ b1) {
    int warp = (blockIdx.x * blockDim.x + threadIdx.x) >> 5;
    if (warp >= NN) return;
    const int lane = threadIdx.x & 31;
    const int node = warp;
    const int h4 = lane >> 2;
    const int beg = g_off[node], end = g_off[node + 1];

    const float er = g_er1[node * HEADS + h4];

    float acc[8];
#pragma unroll
    for (int j = 0; j < 8; j++) acc[j] = 0.f;
    float ssum = 0.f;

    int i = beg;
    for (; i + 2 <= end; i += 2) {
        int s0 = g_psrc[i], s1 = g_psrc[i + 1];
        float a0 = __expf(lrelu(g_el1[s0 * HEADS + h4] + er));
        float a1 = __expf(lrelu(g_el1[s1 * HEADS + h4] + er));
        uint4 u0 = *(const uint4*)&g_f1h[(size_t)s0 * F1DIM + lane * 8];
        uint4 u1 = *(const uint4*)&g_f1h[(size_t)s1 * F1DIM + lane * 8];
        ssum += a0 + a1;
        const __half2* p0 = (const __half2*)&u0;
        const __half2* p1 = (const __half2*)&u1;
#pragma unroll
        for (int j = 0; j < 4; j++) {
            float2 f0 = __half22float2(p0[j]);
            float2 f1 = __half22float2(p1[j]);
            acc[2*j + 0] += a0 * f0.x + a1 * f1.x;
            acc[2*j + 1] += a0 * f0.y + a1 * f1.y;
        }
    }
    if (i < end) {
        int s0 = g_psrc[i];
        float a0 = __expf(lrelu(g_el1[s0 * HEADS + h4] + er));
        uint4 u0 = *(const uint4*)&g_f1h[(size_t)s0 * F1DIM + lane * 8];
        ssum += a0;
        const __half2* p0 = (const __half2*)&u0;
#pragma unroll
        for (int j = 0; j < 4; j++) {
            float2 f0 = __half22float2(p0[j]);
            acc[2*j + 0] += a0 * f0.x;
            acc[2*j + 1] += a0 * f0.y;
        }
    }

    const float inv = ssum > 0.f ? 1.f / ssum : 0.f;
    const float4* bp = (const float4*)&b1[lane * 8];
    float4 bb0 = bp[0], bb1 = bp[1];
    float4* op = (float4*)&g_h[(size_t)node * F1DIM + lane * 8];
    op[0] = make_float4(acc[0] * inv + bb0.x, acc[1] * inv + bb0.y,
                        acc[2] * inv + bb0.z, acc[3] * inv + bb0.w);
    op[1] = make_float4(acc[4] * inv + bb1.x, acc[5] * inv + bb1.y,
                        acc[6] * inv + bb1.z, acc[7] * inv + bb1.w);
}

// ---------------- layer-2 aggregation: warp/node, single pass, fp16 gather ----------
__global__ void __launch_bounds__(256)
agg2(float* __restrict__ out, const float* __restrict__ b2) {
    int warp = (blockIdx.x * blockDim.x + threadIdx.x) >> 5;
    if (warp >= NN) return;
    const int lane = threadIdx.x & 31;
    const int node = warp;
    const int beg = g_off[node], end = g_off[node + 1];

    const float er = g_er2[node];

    float a0 = 0.f, a1 = 0.f, ssum = 0.f;
    int i = beg;
    for (; i + 4 <= end; i += 4) {
        int s0 = g_psrc[i], s1 = g_psrc[i+1], s2 = g_psrc[i+2], s3 = g_psrc[i+3];
        float e0 = __expf(lrelu(g_el2[s0] + er));
        float e1 = __expf(lrelu(g_el2[s1] + er));
        float e2 = __expf(lrelu(g_el2[s2] + er));
        float e3 = __expf(lrelu(g_el2[s3] + er));
        float2 v0 = __half22float2(*(const __half2*)&g_f2h[(size_t)s0 * ODIM + lane * 2]);
        float2 v1 = __half22float2(*(const __half2*)&g_f2h[(size_t)s1 * ODIM + lane * 2]);
        float2 v2 = __half22float2(*(const __half2*)&g_f2h[(size_t)s2 * ODIM + lane * 2]);
        float2 v3 = __half22float2(*(const __half2*)&g_f2h[(size_t)s3 * ODIM + lane * 2]);
        ssum += (e0 + e1) + (e2 + e3);
        a0 += e0 * v0.x + e1 * v1.x + e2 * v2.x + e3 * v3.x;
        a1 += e0 * v0.y + e1 * v1.y + e2 * v2.y + e3 * v3.y;
    }
    for (; i < end; i++) {
        int s = g_psrc[i];
        float e0 = __expf(lrelu(g_el2[s] + er));
        float2 v = __half22float2(*(const __half2*)&g_f2h[(size_t)s * ODIM + lane * 2]);
        ssum += e0;
        a0 += e0 * v.x;
        a1 += e0 * v.y;
    }
    const float inv = ssum > 0.f ? 1.f / ssum : 0.f;
    float2 bb = *(const float2*)&b2[lane * 2];
    *(float2*)&out[(size_t)node * ODIM + lane * 2] = make_float2(a0 * inv + bb.x, a1 * inv + bb.y);
}

// ---------------- launch ----------------
extern "C" void kernel_launch(void* const* d_in, const int* in_sizes, int n_in,
                              void* d_out, int out_size) {
    const float* feat = (const float*)d_in[0];
    const int*   src  = (const int*)  d_in[1];
    const int*   dst  = (const int*)  d_in[2];
    const float* W1   = (const float*)d_in[3];
    const float* al1  = (const float*)d_in[4];
    const float* ar1  = (const float*)d_in[5];
    const float* b1   = (const float*)d_in[6];
    const float* W2   = (const float*)d_in[7];
    const float* al2  = (const float*)d_in[8];
    const float* ar2  = (const float*)d_in[9];
    const float* b2   = (const float*)d_in[10];
    float* out = (float*)d_out;

    float *pf1, *ph, *pf2;
    cudaGetSymbolAddress((void**)&pf1, g_f1);
    cudaGetSymbolAddress((void**)&ph,  g_h);
    cudaGetSymbolAddress((void**)&pf2, g_f2);

    const int T = 256;
    auto cdiv = [](long long a, long long b) { return (int)((a + b - 1) / b); };

    // CSR build (shared by both layers)
    zero_cnt<<<cdiv(NN, T), T>>>();
    count_dst<<<cdiv(NE, T), T>>>(dst);
    scan_off<<<1, 1024>>>();
    place_edges<<<cdiv(NE, T), T>>>(src, dst);

    // Layer 1: f1 = feat @ W1 (tf32 tensor cores)
    gemm_tf32<false><<<dim3(F1DIM/64, NNP/128), 256>>>(feat, W1, pf1, NN, F1DIM, IN_DIM);
    attn_lr1<<<cdiv(NN*HEADS, T), T>>>(al1, ar1);
    agg1<<<cdiv((long long)NN*32, T), T>>>(b1);

    // Layer 2: f2 = ELU(h) @ W2 (ELU fused into A-smem store; h is padded so no A guard)
    gemm_tf32<true><<<dim3(ODIM/64, NNP/128), 256>>>(ph, W2, pf2, NNP, ODIM, F1DIM);
    attn_lr2<<<cdiv(NN, T), T>>>(al2, ar2);
    agg2<<<cdiv((long long)NN*32, T), T>>>(out, b2);
}

// round 12
// speedup vs baseline: 2.4589x; 1.1257x over previous
#include <cuda_runtime.h>
#include <cuda_fp16.h>
#include <mma.h>
#include <math.h>

using namespace nvcuda;

#define NN 50000
#define NNP 50048            // padded rows (= 391 * 128) for unguarded tiles
#define NE 800000
#define IN_DIM 128
#define HID 32
#define HEADS 8
#define F1DIM 256
#define ODIM 64
#define NEG 0.2f
#define FULL 0xffffffffu

// ---------------- scratch (device globals; no allocation) ----------------
__device__ alignas(16) __half g_f1h[(size_t)NN  * F1DIM];  // fp16 gather table, layer 1
__device__ alignas(16) float  g_h  [(size_t)NNP * F1DIM];  // agg1 out; pad rows stay 0 forever
__device__ alignas(16) __half g_f2h[(size_t)NN  * ODIM];   // fp16 gather table, layer 2
__device__ float g_el1[NN * HEADS];
__device__ float g_er1[NN * HEADS];
__device__ float g_el2[NN];
__device__ float g_er2[NN];
__device__ int g_cnt [NN];
__device__ int g_off [NN + 1];
__device__ int g_pos [NN];
__device__ int g_psrc[NE];

__device__ __forceinline__ float lrelu(float x) { return x >= 0.f ? x : NEG * x; }

// ---------------- CSR build ----------------
__global__ void zero_cnt() {
    int i = blockIdx.x * blockDim.x + threadIdx.x;
    if (i < NN) g_cnt[i] = 0;
}
__global__ void count_dst(const int* __restrict__ dst) {
    int e = blockIdx.x * blockDim.x + threadIdx.x;
    if (e < NE) atomicAdd(&g_cnt[dst[e]], 1);
}
__global__ void scan_off() {
    __shared__ int wsum[32];
    const int t = threadIdx.x;
    const int C = (NN + 1023) / 1024;
    const int base = t * C;
    int s = 0;
    for (int j = 0; j < C; j++) { int idx = base + j; if (idx < NN) s += g_cnt[idx]; }
    int lane = t & 31, wid = t >> 5;
    int v = s;
#pragma unroll
    for (int o = 1; o < 32; o <<= 1) { int n = __shfl_up_sync(FULL, v, o); if (lane >= o) v += n; }
    if (lane == 31) wsum[wid] = v;
    __syncthreads();
    if (wid == 0) {
        int w = wsum[lane];
#pragma unroll
        for (int o = 1; o < 32; o <<= 1) { int n = __shfl_up_sync(FULL, w, o); if (lane >= o) w += n; }
        wsum[lane] = w;
    }
    __syncthreads();
    int run = (v - s) + (wid > 0 ? wsum[wid - 1] : 0);
    for (int j = 0; j < C; j++) {
        int idx = base + j;
        if (idx < NN) { g_off[idx] = run; g_pos[idx] = run; run += g_cnt[idx]; }
    }
    if (t == 1023) g_off[NN] = NE;
}
__global__ void place_edges(const int* __restrict__ src, const int* __restrict__ dst) {
    int e = blockIdx.x * blockDim.x + threadIdx.x;
    if (e >= NE) return;
    int slot = atomicAdd(&g_pos[dst[e]], 1);
    g_psrc[slot] = src[e];
}

// ---------------- tf32 GEMM with fused attention epilogue ----------------
// C-tile (128x64) never hits global fp32: staged via smem, epilogue emits
//   fp16 message table + per-row attention dots el/er.
// EPI==1: layer 1 (2 heads per col-block, HID=32).  EPI==2: layer 2 (1 head, 64 dims).
// ELUA: apply ELU on A-tile load (layer 2 reads g_h).
#define LDA 40
#define LDB 72
#define LDC 68
template<bool ELUA, int EPI>
__global__ void __launch_bounds__(256, 2)
gemm_fused(const float* __restrict__ A, const float* __restrict__ B,
           const float* __restrict__ av, const float* __restrict__ rv,
           int M, int K, int Nn) {
    __shared__ float sbuf[128 * LDC];          // 34.8 KB; As+Bs live in the front
    float* As = sbuf;                          // [128][LDA]
    float* Bs = sbuf + 128 * LDA;              // [32][LDB]
    const int tid = threadIdx.x;
    const int wid = tid >> 5;
    const int wm = (wid & 3) * 32;
    const int wn = (wid >> 2) * 32;
    const int rowBase = blockIdx.y * 128;
    const int colBase = blockIdx.x * 64;

    int aRow[4], aK[4];
#pragma unroll
    for (int l = 0; l < 4; l++) {
        int f = tid + l * 256;
        aRow[l] = f >> 3; aK[l] = (f & 7) * 4;
    }
    int bRow[2], bCol[2];
#pragma unroll
    for (int l = 0; l < 2; l++) {
        int f = tid + l * 256;
        bRow[l] = f >> 4; bCol[l] = (f & 15) * 4;
    }

    wmma::fragment<wmma::accumulator, 16, 16, 8, float> acc[2][2];
#pragma unroll
    for (int i = 0; i < 2; i++)
#pragma unroll
        for (int j = 0; j < 2; j++) wmma::fill_fragment(acc[i][j], 0.f);

    float4 pa[4], pb[2];
#pragma unroll
    for (int l = 0; l < 4; l++) {
        pa[l] = make_float4(0.f, 0.f, 0.f, 0.f);
        if (rowBase + aRow[l] < M) pa[l] = *(const float4*)&A[(size_t)(rowBase + aRow[l]) * K + aK[l]];
    }
#pragma unroll
    for (int l = 0; l < 2; l++)
        pb[l] = *(const float4*)&B[(size_t)bRow[l] * Nn + colBase + bCol[l]];

    for (int k0 = 0; k0 < K; k0 += 32) {
#pragma unroll
        for (int l = 0; l < 4; l++) {
            float4 sa = pa[l];
            if (ELUA) {
                sa.x = sa.x > 0.f ? sa.x : expm1f(sa.x);
                sa.y = sa.y > 0.f ? sa.y : expm1f(sa.y);
                sa.z = sa.z > 0.f ? sa.z : expm1f(sa.z);
                sa.w = sa.w > 0.f ? sa.w : expm1f(sa.w);
            }
            float* p = &As[aRow[l] * LDA + aK[l]];
            p[0] = sa.x; p[1] = sa.y; p[2] = sa.z; p[3] = sa.w;
        }
#pragma unroll
        for (int l = 0; l < 2; l++) {
            float* p = &Bs[bRow[l] * LDB + bCol[l]];
            p[0] = pb[l].x; p[1] = pb[l].y; p[2] = pb[l].z; p[3] = pb[l].w;
        }
        __syncthreads();

        if (k0 + 32 < K) {
#pragma unroll
            for (int l = 0; l < 4; l++)
                if (rowBase + aRow[l] < M)
                    pa[l] = *(const float4*)&A[(size_t)(rowBase + aRow[l]) * K + (k0 + 32) + aK[l]];
#pragma unroll
            for (int l = 0; l < 2; l++)
                pb[l] = *(const float4*)&B[(size_t)(k0 + 32 + bRow[l]) * Nn + colBase + bCol[l]];
        }

#pragma unroll
        for (int kk = 0; kk < 32; kk += 8) {
            wmma::fragment<wmma::matrix_a, 16, 16, 8, wmma::precision::tf32, wmma::row_major> af[2];
            wmma::fragment<wmma::matrix_b, 16, 16, 8, wmma::precision::tf32, wmma::row_major> bf[2];
#pragma unroll
            for (int i = 0; i < 2; i++) {
                wmma::load_matrix_sync(af[i], &As[(wm + i * 16) * LDA + kk], LDA);
#pragma unroll
                for (int t = 0; t < af[i].num_elements; t++)
                    af[i].x[t] = wmma::__float_to_tf32(af[i].x[t]);
            }
#pragma unroll
            for (int j = 0; j < 2; j++) {
                wmma::load_matrix_sync(bf[j], &Bs[kk * LDB + wn + j * 16], LDB);
#pragma unroll
                for (int t = 0; t < bf[j].num_elements; t++)
                    bf[j].x[t] = wmma::__float_to_tf32(bf[j].x[t]);
            }
#pragma unroll
            for (int i = 0; i < 2; i++)
#pragma unroll
                for (int j = 0; j < 2; j++)
                    wmma::mma_sync(acc[i][j], af[i], bf[j], acc[i][j]);
        }
        __syncthreads();
    }

    // ---- epilogue: stage tile in smem, emit el/er + fp16 table ----
#pragma unroll
    for (int i = 0; i < 2; i++)
#pragma unroll
        for (int j = 0; j < 2; j++)
            wmma::store_matrix_sync(&sbuf[(wm + i * 16) * LDC + wn + j * 16], acc[i][j],
                                    LDC, wmma::mem_row_major);
    __syncthreads();

    const int row  = tid >> 1;
    const int half = tid & 1;
    const int gr   = rowBase + row;
    const float* crow = &sbuf[row * LDC + half * 32];
    const int head = (EPI == 1) ? ((colBase >> 5) + half) : 0;
    const float* ap = (EPI == 1) ? av + head * HID : av + half * 32;
    const float* rp = (EPI == 1) ? rv + head * HID : rv + half * 32;

    float el = 0.f, er = 0.f;
    unsigned w[16];
#pragma unroll
    for (int d = 0; d < 32; d += 2) {
        float c0 = crow[d], c1 = crow[d + 1];
        el += c0 * ap[d] + c1 * ap[d + 1];
        er += c0 * rp[d] + c1 * rp[d + 1];
        __half2 hh = __floats2half2_rn(c0, c1);
        w[d >> 1] = *(unsigned*)&hh;
    }

    if (EPI == 1) {
        if (gr < NN) {
            g_el1[gr * HEADS + head] = el;
            g_er1[gr * HEADS + head] = er;
            uint4* d4 = (uint4*)&g_f1h[(size_t)gr * F1DIM + colBase + half * 32];
            const uint4* s4 = (const uint4*)w;
            d4[0] = s4[0]; d4[1] = s4[1]; d4[2] = s4[2]; d4[3] = s4[3];
        }
    } else {
        // full 64-dim dot: combine the two halves (computed unconditionally -> converged)
        float elf = el + __shfl_xor_sync(FULL, el, 1);
        float erf = er + __shfl_xor_sync(FULL, er, 1);
        if (gr < NN) {
            if (half == 0) { g_el2[gr] = elf; g_er2[gr] = erf; }
            uint4* d4 = (uint4*)&g_f2h[(size_t)gr * ODIM + half * 32];
            const uint4* s4 = (const uint4*)w;
            d4[0] = s4[0]; d4[1] = s4[1]; d4[2] = s4[2]; d4[3] = s4[3];
        }
    }
}

// ---------------- layer-1 aggregation: warp/node, single pass, fp16 gather ----------
__global__ void __launch_bounds__(256)
agg1(const float* __restrict__ b1) {
    int warp = (blockIdx.x * blockDim.x + threadIdx.x) >> 5;
    if (warp >= NN) return;
    const int lane = threadIdx.x & 31;
    const int node = warp;
    const int h4 = lane >> 2;
    const int beg = g_off[node], end = g_off[node + 1];

    const float er = g_er1[node * HEADS + h4];

    float acc[8];
#pragma unroll
    for (int j = 0; j < 8; j++) acc[j] = 0.f;
    float ssum = 0.f;

    int i = beg;
    for (; i + 2 <= end; i += 2) {
        int s0 = g_psrc[i], s1 = g_psrc[i + 1];
        float a0 = __expf(lrelu(g_el1[s0 * HEADS + h4] + er));
        float a1 = __expf(lrelu(g_el1[s1 * HEADS + h4] + er));
        uint4 u0 = *(const uint4*)&g_f1h[(size_t)s0 * F1DIM + lane * 8];
        uint4 u1 = *(const uint4*)&g_f1h[(size_t)s1 * F1DIM + lane * 8];
        ssum += a0 + a1;
        const __half2* p0 = (const __half2*)&u0;
        const __half2* p1 = (const __half2*)&u1;
#pragma unroll
        for (int j = 0; j < 4; j++) {
            float2 f0 = __half22float2(p0[j]);
            float2 f1 = __half22float2(p1[j]);
            acc[2*j + 0] += a0 * f0.x + a1 * f1.x;
            acc[2*j + 1] += a0 * f0.y + a1 * f1.y;
        }
    }
    if (i < end) {
        int s0 = g_psrc[i];
        float a0 = __expf(lrelu(g_el1[s0 * HEADS + h4] + er));
        uint4 u0 = *(const uint4*)&g_f1h[(size_t)s0 * F1DIM + lane * 8];
        ssum += a0;
        const __half2* p0 = (const __half2*)&u0;
#pragma unroll
        for (int j = 0; j < 4; j++) {
            float2 f0 = __half22float2(p0[j]);
            acc[2*j + 0] += a0 * f0.x;
            acc[2*j + 1] += a0 * f0.y;
        }
    }

    const float inv = ssum > 0.f ? 1.f / ssum : 0.f;
    const float4* bp = (const float4*)&b1[lane * 8];
    float4 bb0 = bp[0], bb1 = bp[1];
    float4* op = (float4*)&g_h[(size_t)node * F1DIM + lane * 8];
    op[0] = make_float4(acc[0] * inv + bb0.x, acc[1] * inv + bb0.y,
                        acc[2] * inv + bb0.z, acc[3] * inv + bb0.w);
    op[1] = make_float4(acc[4] * inv + bb1.x, acc[5] * inv + bb1.y,
                        acc[6] * inv + bb1.z, acc[7] * inv + bb1.w);
}

// ---------------- layer-2 aggregation: warp/node, single pass, fp16 gather ----------
__global__ void __launch_bounds__(256)
agg2(float* __restrict__ out, const float* __restrict__ b2) {
    int warp = (blockIdx.x * blockDim.x + threadIdx.x) >> 5;
    if (warp >= NN) return;
    const int lane = threadIdx.x & 31;
    const int node = warp;
    const int beg = g_off[node], end = g_off[node + 1];

    const float er = g_er2[node];

    float a0 = 0.f, a1 = 0.f, ssum = 0.f;
    int i = beg;
    for (; i + 4 <= end; i += 4) {
        int s0 = g_psrc[i], s1 = g_psrc[i+1], s2 = g_psrc[i+2], s3 = g_psrc[i+3];
        float e0 = __expf(lrelu(g_el2[s0] + er));
        float e1 = __expf(lrelu(g_el2[s1] + er));
        float e2 = __expf(lrelu(g_el2[s2] + er));
        float e3 = __expf(lrelu(g_el2[s3] + er));
        float2 v0 = __half22float2(*(const __half2*)&g_f2h[(size_t)s0 * ODIM + lane * 2]);
        float2 v1 = __half22float2(*(const __half2*)&g_f2h[(size_t)s1 * ODIM + lane * 2]);
        float2 v2 = __half22float2(*(const __half2*)&g_f2h[(size_t)s2 * ODIM + lane * 2]);
        float2 v3 = __half22float2(*(const __half2*)&g_f2h[(size_t)s3 * ODIM + lane * 2]);
        ssum += (e0 + e1) + (e2 + e3);
        a0 += e0 * v0.x + e1 * v1.x + e2 * v2.x + e3 * v3.x;
        a1 += e0 * v0.y + e1 * v1.y + e2 * v2.y + e3 * v3.y;
    }
    for (; i < end; i++) {
        int s = g_psrc[i];
        float e0 = __expf(lrelu(g_el2[s] + er));
        float2 v = __half22float2(*(const __half2*)&g_f2h[(size_t)s * ODIM + lane * 2]);
        ssum += e0;
        a0 += e0 * v.x;
        a1 += e0 * v.y;
    }
    const float inv = ssum > 0.f ? 1.f / ssum : 0.f;
    float2 bb = *(const float2*)&b2[lane * 2];
    *(float2*)&out[(size_t)node * ODIM + lane * 2] = make_float2(a0 * inv + bb.x, a1 * inv + bb.y);
}

// ---------------- launch ----------------
extern "C" void kernel_launch(void* const* d_in, const int* in_sizes, int n_in,
                              void* d_out, int out_size) {
    const float* feat = (const float*)d_in[0];
    const int*   src  = (const int*)  d_in[1];
    const int*   dst  = (const int*)  d_in[2];
    const float* W1   = (const float*)d_in[3];
    const float* al1  = (const float*)d_in[4];
    const float* ar1  = (const float*)d_in[5];
    const float* b1   = (const float*)d_in[6];
    const float* W2   = (const float*)d_in[7];
    const float* al2  = (const float*)d_in[8];
    const float* ar2  = (const float*)d_in[9];
    const float* b2   = (const float*)d_in[10];
    float* out = (float*)d_out;

    float* ph;
    cudaGetSymbolAddress((void**)&ph, g_h);

    const int T = 256;
    auto cdiv = [](long long a, long long b) { return (int)((a + b - 1) / b); };

    // CSR build (shared by both layers)
    zero_cnt<<<cdiv(NN, T), T>>>();
    count_dst<<<cdiv(NE, T), T>>>(dst);
    scan_off<<<1, 1024>>>();
    place_edges<<<cdiv(NE, T), T>>>(src, dst);

    // Layer 1: f1h/el1/er1 = fused(feat @ W1)
    gemm_fused<false, 1><<<dim3(F1DIM / 64, NNP / 128), 256>>>(feat, W1, al1, ar1, NN, IN_DIM, F1DIM);
    agg1<<<cdiv((long long)NN * 32, T), T>>>(b1);

    // Layer 2: f2h/el2/er2 = fused(ELU(g_h) @ W2); g_h pad rows are永 0 -> safe
    gemm_fused<true, 2><<<dim3(ODIM / 64, NNP / 128), 256>>>(ph, W2, al2, ar2, NNP, F1DIM, ODIM);
    agg2<<<cdiv((long long)NN * 32, T), T>>>(out, b2);
}